// round 4
// baseline (speedup 1.0000x reference)
#include <cuda_runtime.h>
#include <cstdint>

// Problem constants
#define S_LEN   512
#define BATCH   64
#define HID     512
#define GCOLS   2048          // 4*H
#define NCTA    128           // 2048 gate cols / 16 per CTA (4 h-cols x 4 gates)
#define NTHR    128
#define CHUNK   128           // K chunk staged in smem
#define INS_STRIDE 132        // 128 + 4 pad (conflict-free LDS.128 across rows)
#define BUFSZ   (BATCH * INS_STRIDE)   // 8448 floats per input buffer
#define WCHUNK  (CHUNK * 16)           // 2048 floats per weight chunk

typedef unsigned long long ull;

// ---- persistent device state (allocation-free rule: __device__ globals) ----
__device__ __align__(128) float g_h0[2][BATCH * HID];
__device__ __align__(128) float g_h1[2][BATCH * HID];
__device__ __align__(128) float g_c0[BATCH * HID];
__device__ __align__(128) float g_c1[BATCH * HID];
// packed weights: [layer][cta*16384 + kp*32 + hl*8 + g*2 + e]
__device__ __align__(128) float g_wpack[2][NCTA * 16384];

// ---------------- cp.async helpers ----------------
__device__ __forceinline__ void cpa16(uint32_t dst, const float* src) {
    asm volatile("cp.async.cg.shared.global [%0], [%1], 16;\n" :: "r"(dst), "l"(src));
}
__device__ __forceinline__ void cp_commit() { asm volatile("cp.async.commit_group;\n" ::: "memory"); }
__device__ __forceinline__ void cp_wait1()  { asm volatile("cp.async.wait_group 1;\n" ::: "memory"); }
__device__ __forceinline__ void cp_wait0()  { asm volatile("cp.async.wait_group 0;\n" ::: "memory"); }

// ---------------- packed fp32x2 helpers ----------------
__device__ __forceinline__ ull ffma2(ull x, ull w, ull acc) {
    asm("fma.rn.f32x2 %0, %1, %2, %0;" : "+l"(acc) : "l"(x), "l"(w));
    return acc;
}
__device__ __forceinline__ ull pack2(float lo, float hi) {
    ull r; asm("mov.b64 %0, {%1, %2};" : "=l"(r) : "f"(lo), "f"(hi)); return r;
}
__device__ __forceinline__ float sum2(ull v) {
    float lo, hi; asm("mov.b64 {%0, %1}, %2;" : "=f"(lo), "=f"(hi) : "l"(v));
    return lo + hi;
}

// Stage one [64 x 128] fp32 input chunk into smem (row stride INS_STRIDE).
__device__ __forceinline__ void stage_chunk(float* dst, const float* gbase, int tid) {
#pragma unroll
    for (int i = 0; i < 16; i++) {
        int idx = i * NTHR + tid;
        int row = idx >> 5;           // 0..63
        int q   = idx & 31;           // float4 index within row
        uint32_t d = (uint32_t)__cvta_generic_to_shared(dst + row * INS_STRIDE + q * 4);
        cpa16(d, gbase + row * HID + q * 4);
    }
}

// Stage one 8KB weight chunk (contiguous in packed layout).
__device__ __forceinline__ void stage_wchunk(float* dst, const float* src, int tid) {
#pragma unroll
    for (int i = 0; i < 4; i++) {
        int idx = i * NTHR + tid;
        cpa16((uint32_t)__cvta_generic_to_shared(dst + idx * 4), src + idx * 4);
    }
}

// One gate-GEMM phase: acc += concat(src0,src1)[rows rA,rB] @ W[:, 16 cols].
// K=1024 as 8 double-buffered chunks (input + weights both cp.async-staged).
__device__ __forceinline__ void run_phase(const float* __restrict__ wg,   // packed weights (global)
                                          float* __restrict__ wsm,       // 2 x WCHUNK smem
                                          float* __restrict__ ins,       // 2 x BUFSZ smem
                                          const float* __restrict__ src0,
                                          const float* __restrict__ src1,
                                          int tid, int rA, int rB, int hl,
                                          ull aA[4], ull aB[4]) {
    stage_chunk(ins, src0, tid);          // chunk 0 (k<512 -> src0)
    stage_wchunk(wsm, wg, tid);
    cp_commit();
#pragma unroll 1
    for (int c = 0; c < 8; c++) {
        if (c < 7) {
            int kk = (c + 1) * CHUNK;
            const float* gb = (kk < HID) ? (src0 + kk) : (src1 + (kk - HID));
            stage_chunk(ins + ((c + 1) & 1) * BUFSZ, gb, tid);
            stage_wchunk(wsm + ((c + 1) & 1) * WCHUNK, wg + (c + 1) * WCHUNK, tid);
            cp_commit();
            cp_wait1();                   // chunk c landed
        } else {
            cp_wait0();
        }
        __syncthreads();

        const float* bf = ins + (c & 1) * BUFSZ;
        const ull*   wc = (const ull*)(wsm + (c & 1) * WCHUNK) + (hl << 2);
        const float* hA = bf + rA * INS_STRIDE;
        const float* hB = bf + rB * INS_STRIDE;
#pragma unroll 4
        for (int kp = 0; kp < CHUNK / 2; kp += 2) {   // 4 k per iteration
            ulonglong2 a2 = *(const ulonglong2*)(hA + 2 * kp);   // (k,k+1),(k+2,k+3)
            ulonglong2 b2 = *(const ulonglong2*)(hB + 2 * kp);
            const ull* w0 = wc + (kp << 4);
            ulonglong2 w0a = *(const ulonglong2*)(w0);        // gates 0,1 for pair kp
            ulonglong2 w0b = *(const ulonglong2*)(w0 + 2);    // gates 2,3
            ulonglong2 w1a = *(const ulonglong2*)(w0 + 16);   // pair kp+1
            ulonglong2 w1b = *(const ulonglong2*)(w0 + 18);
            aA[0] = ffma2(a2.x, w0a.x, aA[0]);  aB[0] = ffma2(b2.x, w0a.x, aB[0]);
            aA[1] = ffma2(a2.x, w0a.y, aA[1]);  aB[1] = ffma2(b2.x, w0a.y, aB[1]);
            aA[2] = ffma2(a2.x, w0b.x, aA[2]);  aB[2] = ffma2(b2.x, w0b.x, aB[2]);
            aA[3] = ffma2(a2.x, w0b.y, aA[3]);  aB[3] = ffma2(b2.x, w0b.y, aB[3]);
            aA[0] = ffma2(a2.y, w1a.x, aA[0]);  aB[0] = ffma2(b2.y, w1a.x, aB[0]);
            aA[1] = ffma2(a2.y, w1a.y, aA[1]);  aB[1] = ffma2(b2.y, w1a.y, aB[1]);
            aA[2] = ffma2(a2.y, w1b.x, aA[2]);  aB[2] = ffma2(b2.y, w1b.x, aB[2]);
            aA[3] = ffma2(a2.y, w1b.y, aA[3]);  aB[3] = ffma2(b2.y, w1b.y, aB[3]);
        }
        __syncthreads();
    }
}

__device__ __forceinline__ float sigmoidf_(float x) { return 1.0f / (1.0f + __expf(-x)); }

// gates order per reference split: f, i1, i2, o
__device__ __forceinline__ float lstm_cell(const ull acc[4], float& c) {
    float f  = sigmoidf_(sum2(acc[0]));
    float i1 = sigmoidf_(sum2(acc[1]));
    float i2 = tanhf(sum2(acc[2]));
    float o  = sigmoidf_(sum2(acc[3]));
    c = f * c + i1 * i2;
    return o * tanhf(c);
}

// ---- one-time per replay: repack weights into per-CTA paired-k layout ----
__global__ void pack_kernel(const float* __restrict__ Wx0, const float* __restrict__ Wh0,
                            const float* __restrict__ Wx1, const float* __restrict__ Wh1) {
    int cta = blockIdx.x;
    for (int idx = threadIdx.x; idx < 16384; idx += blockDim.x) {
        int e  = idx & 1;
        int g  = (idx >> 1) & 3;
        int hh = (idx >> 3) & 3;
        int kp = idx >> 5;
        int k  = kp * 2 + e;
        int col = g * HID + cta * 4 + hh;
        g_wpack[0][cta * 16384 + idx] =
            (k < HID) ? Wx0[k * GCOLS + col] : Wh0[(k - HID) * GCOLS + col];
        g_wpack[1][cta * 16384 + idx] =
            (k < HID) ? Wx1[k * GCOLS + col] : Wh1[(k - HID) * GCOLS + col];
    }
}

// ---- zero h ping-pong buffers and cell states (each replay: determinism) ----
__global__ void init_kernel() {
    int idx = blockIdx.x * blockDim.x + threadIdx.x;
    if (idx < BATCH * HID) {
        g_h0[0][idx] = 0.f; g_h0[1][idx] = 0.f;
        g_h1[0][idx] = 0.f; g_h1[1][idx] = 0.f;
        g_c0[idx] = 0.f;    g_c1[idx] = 0.f;
    }
}

// ---- skewed step: launch k does layer0(step k) and layer1(step k-1).
// Both read only data produced by launch k-1 (parity buffers), so the two
// phases never race across blocks. Kernel boundary = global sync.
__global__ __launch_bounds__(NTHR, 1)
void step_kernel(const float* __restrict__ x,
                 const float* __restrict__ b0, const float* __restrict__ b1,
                 float* __restrict__ out, int k) {
    extern __shared__ float sm[];
    float* ins = sm;                  // 2 x BUFSZ
    float* wsm = sm + 2 * BUFSZ;      // 2 x WCHUNK

    const int tid = threadIdx.x;
    const int cta = blockIdx.x;
    const int r   = tid & 31;
    const int hl  = tid >> 5;         // 0..3 (uniform per warp -> weight broadcast)
    const int hc  = cta * 4 + hl;     // owned h-column
    const int rA = r, rB = r + 32;
    const int p = k & 1, q = p ^ 1;

    // ---- phase A: layer 0, step k ----
    if (k < S_LEN) {
        ull aA[4], aB[4];
#pragma unroll
        for (int g = 0; g < 4; g++) {              // reference adds b twice -> 2*b
            float bv = 2.0f * b0[g * HID + hc];
            aA[g] = pack2(bv, 0.f); aB[g] = pack2(bv, 0.f);
        }
        run_phase(g_wpack[0] + cta * 16384, wsm, ins,
                  x + (size_t)k * BATCH * HID, g_h0[p], tid, rA, rB, hl, aA, aB);
        float cA = g_c0[rA * HID + hc], cB = g_c0[rB * HID + hc];
        float hA = lstm_cell(aA, cA);
        float hB = lstm_cell(aB, cB);
        g_c0[rA * HID + hc] = cA;      g_c0[rB * HID + hc] = cB;
        g_h0[q][rA * HID + hc] = hA;   g_h0[q][rB * HID + hc] = hB;
    }

    // ---- phase B: layer 1, step k-1 (reads h0 produced by PREVIOUS launch) ----
    if (k > 0) {
        const int s = k - 1;
        ull aA[4], aB[4];
#pragma unroll
        for (int g = 0; g < 4; g++) {
            float bv = 2.0f * b1[g * HID + hc];
            aA[g] = pack2(bv, 0.f); aB[g] = pack2(bv, 0.f);
        }
        run_phase(g_wpack[1] + cta * 16384, wsm, ins,
                  g_h0[p], g_h1[p], tid, rA, rB, hl, aA, aB);
        float cA = g_c1[rA * HID + hc], cB = g_c1[rB * HID + hc];
        float hA = lstm_cell(aA, cA);
        float hB = lstm_cell(aB, cB);
        g_c1[rA * HID + hc] = cA;      g_c1[rB * HID + hc] = cB;
        g_h1[q][rA * HID + hc] = hA;   g_h1[q][rB * HID + hc] = hB;
        out[(size_t)s * BATCH * HID + rA * HID + hc] = hA;
        out[(size_t)s * BATCH * HID + rB * HID + hc] = hB;
    }
}

extern "C" void kernel_launch(void* const* d_in, const int* in_sizes, int n_in,
                              void* d_out, int out_size) {
    const float* x   = (const float*)d_in[0];
    const float* Wx0 = (const float*)d_in[1];
    const float* Wh0 = (const float*)d_in[2];
    const float* b0  = (const float*)d_in[3];
    const float* Wx1 = (const float*)d_in[4];
    const float* Wh1 = (const float*)d_in[5];
    const float* b1  = (const float*)d_in[6];
    float* out = (float*)d_out;

    size_t smem = (size_t)(2 * BUFSZ + 2 * WCHUNK) * sizeof(float);  // ~84 KB
    static int attr_done = 0;
    if (!attr_done) {   // host-side attribute set; idempotent and capture-safe
        cudaFuncSetAttribute(step_kernel,
                             cudaFuncAttributeMaxDynamicSharedMemorySize, (int)smem);
        attr_done = 1;
    }

    pack_kernel<<<NCTA, 256>>>(Wx0, Wh0, Wx1, Wh1);
    init_kernel<<<(BATCH * HID + 255) / 256, 256>>>();
    for (int k = 0; k <= S_LEN; k++) {
        step_kernel<<<NCTA, NTHR, smem>>>(x, b0, b1, out, k);
    }
}